// round 9
// baseline (speedup 1.0000x reference)
#include <cuda_runtime.h>
#include <cstdint>

typedef unsigned long long u64;

#define NSH 10      // split-K for head GEMMs (N=1024)
#define NSG 3       // split-K for GRU gate GEMMs (N=4096)
static const float UNI = (float)(0.01 / 32.0);

// ---------------- static device scratch (no allocations) ----------------
__device__ float g_tokT[64 * 4096 * 16];     // tokens transposed [t][k][b]
__device__ float g_deterT[4096 * 16];        // deter transposed [n][b]
__device__ float g_xT[1024 * 16];            // GRU input x transposed
__device__ float g_hQ[1024 * 16];            // prior hidden (transposed)
__device__ float g_hP[1024 * 16];            // post hidden (transposed)
__device__ float g_partQ[NSH * 16 * 1024];
__device__ float g_partP[NSH * 16 * 1024];
__device__ float g_partZ[NSG * 16 * 4096];
__device__ float g_partC[NSG * 16 * 4096];
__device__ unsigned g_cnt;
__device__ volatile unsigned g_epoch;

struct P32 {
    const float *tokens, *actions, *gpost, *gprior;
    const float *pW1,*pb1,*pg1,*pB1,*pW2,*pb2,*pg2,*pB2,*pWo,*pbo;
    const float *qW1,*qb1,*qg1,*qB1,*qW2,*qb2,*qg2,*qB2,*qWo,*qbo;
    const float *gW,*gb,*gg,*gB,*gWz,*gbz,*gWc,*gbc;
    float* out;
    int G;
};

// ---------------- grid-wide barrier (all G blocks co-resident) ----------------
__device__ __forceinline__ void gsync(int G, unsigned& ep) {
    __syncthreads();
    ep += 1;
    if (threadIdx.x == 0) {
        __threadfence();                      // make my writes L2-visible
        unsigned v = atomicAdd(&g_cnt, 1u);
        if (v == (unsigned)(G - 1)) {
            atomicExch(&g_cnt, 0u);
            __threadfence();
            g_epoch = ep;
        } else {
            while (g_epoch < ep) { __nanosleep(64); }
        }
        __threadfence();                      // gpu-scope fence -> L1 invalidate
    }
    __syncthreads();
}

// ---------------- block reduction helper (1024 threads) ----------------
__device__ __forceinline__ float block_sum(float v, float* sh) {
    #pragma unroll
    for (int o = 16; o > 0; o >>= 1) v += __shfl_xor_sync(0xffffffffu, v, o);
    int w = threadIdx.x >> 5;
    if ((threadIdx.x & 31) == 0) sh[w] = v;
    __syncthreads();
    if (threadIdx.x < 32) {
        float r = sh[threadIdx.x];
        #pragma unroll
        for (int o = 16; o > 0; o >>= 1) r += __shfl_xor_sync(0xffffffffu, r, o);
        if (threadIdx.x == 0) sh[0] = r;
    }
    __syncthreads();
    float r = sh[0];
    __syncthreads();
    return r;
}

// ---------------- block-task GEMM: P[sp] = X[16,K] @ W[K,N] column tile ----------------
// X virtual concat of A0 (len0 k's) and A1, both transposed [k][16].
// Block task = 128 cols x K/NS. Warp = 4 cols/lane x 8 rows; 16 k-subranges x 2 row halves.
// Per k: 1 LDG.128 (4 w cols) + 2 LDG.128 (x broadcast, L1) + 16 fma.rn.f32x2.
__device__ void gemm_task(
    int task,
    const float* __restrict__ A0, int len0, const float* __restrict__ A1,
    const float* __restrict__ W, int N, int K, int NS,
    float* __restrict__ P, float* __restrict__ sm)
{
    const int nCT = N >> 7;
    const int ct = task % nCT, sp = task / nCT;
    const int kb = (int)(((long long)sp * K) / NS);
    const int ke = (int)(((long long)(sp + 1) * K) / NS);
    const int kl = ke - kb;
    const int w = threadIdx.x >> 5, lane = threadIdx.x & 31;
    const int rh = w & 1, ks = w >> 1;
    const int wk0 = kb + (int)(((long long)kl * ks) >> 4);
    const int wk1 = kb + (int)(((long long)kl * (ks + 1)) >> 4);
    const int col = (ct << 7) + lane * 4;

    u64 acc[16];
    #pragma unroll
    for (int i = 0; i < 16; ++i) acc[i] = 0ull;

    #pragma unroll 1
    for (int seg = 0; seg < 2; ++seg) {
        int ka = seg ? (wk0 > len0 ? wk0 : len0) : wk0;
        int kz = seg ? wk1 : (wk1 < len0 ? wk1 : len0);
        if (ka >= kz) continue;
        const float* X  = (seg ? A1 + ((long long)(ka - len0) * 16)
                               : A0 + ((long long)ka * 16)) + rh * 8;
        const float* wp = W + (long long)ka * N + col;
        int n = kz - ka;
        #pragma unroll 2
        for (int k = 0; k < n; ++k) {
            float4 wv = *(const float4*)wp;
            ulonglong2 xa = *(const ulonglong2*)X;
            ulonglong2 xb = *(const ulonglong2*)(X + 4);
            u64 xs0 = xa.x, xs1 = xa.y, xs2 = xb.x, xs3 = xb.y;
            u64 wd;
            asm("mov.b64 %0, {%1, %1};" : "=l"(wd) : "f"(wv.x));
            asm("fma.rn.f32x2 %0, %1, %2, %0;" : "+l"(acc[0])  : "l"(xs0), "l"(wd));
            asm("fma.rn.f32x2 %0, %1, %2, %0;" : "+l"(acc[1])  : "l"(xs1), "l"(wd));
            asm("fma.rn.f32x2 %0, %1, %2, %0;" : "+l"(acc[2])  : "l"(xs2), "l"(wd));
            asm("fma.rn.f32x2 %0, %1, %2, %0;" : "+l"(acc[3])  : "l"(xs3), "l"(wd));
            asm("mov.b64 %0, {%1, %1};" : "=l"(wd) : "f"(wv.y));
            asm("fma.rn.f32x2 %0, %1, %2, %0;" : "+l"(acc[4])  : "l"(xs0), "l"(wd));
            asm("fma.rn.f32x2 %0, %1, %2, %0;" : "+l"(acc[5])  : "l"(xs1), "l"(wd));
            asm("fma.rn.f32x2 %0, %1, %2, %0;" : "+l"(acc[6])  : "l"(xs2), "l"(wd));
            asm("fma.rn.f32x2 %0, %1, %2, %0;" : "+l"(acc[7])  : "l"(xs3), "l"(wd));
            asm("mov.b64 %0, {%1, %1};" : "=l"(wd) : "f"(wv.z));
            asm("fma.rn.f32x2 %0, %1, %2, %0;" : "+l"(acc[8])  : "l"(xs0), "l"(wd));
            asm("fma.rn.f32x2 %0, %1, %2, %0;" : "+l"(acc[9])  : "l"(xs1), "l"(wd));
            asm("fma.rn.f32x2 %0, %1, %2, %0;" : "+l"(acc[10]) : "l"(xs2), "l"(wd));
            asm("fma.rn.f32x2 %0, %1, %2, %0;" : "+l"(acc[11]) : "l"(xs3), "l"(wd));
            asm("mov.b64 %0, {%1, %1};" : "=l"(wd) : "f"(wv.w));
            asm("fma.rn.f32x2 %0, %1, %2, %0;" : "+l"(acc[12]) : "l"(xs0), "l"(wd));
            asm("fma.rn.f32x2 %0, %1, %2, %0;" : "+l"(acc[13]) : "l"(xs1), "l"(wd));
            asm("fma.rn.f32x2 %0, %1, %2, %0;" : "+l"(acc[14]) : "l"(xs2), "l"(wd));
            asm("fma.rn.f32x2 %0, %1, %2, %0;" : "+l"(acc[15]) : "l"(xs3), "l"(wd));
            X += 16; wp += N;
        }
    }

    // cross-warp split-K reduce: 4 rounds of 8 warps through 33-stride smem
    float psum0 = 0.f, psum1 = 0.f;
    const int tid = threadIdx.x;
    #pragma unroll 1
    for (int round = 0; round < 4; ++round) {
        if ((ks >> 2) == round) {
            int slot = ((ks & 3) << 1) | rh;
            float* dst = sm + (slot * 32 + lane) * 33;
            #pragma unroll
            for (int c = 0; c < 4; ++c)
                #pragma unroll
                for (int j = 0; j < 4; ++j) {
                    float lo, hi;
                    asm("mov.b64 {%0, %1}, %2;" : "=f"(lo), "=f"(hi) : "l"(acc[c*4+j]));
                    dst[c*8 + j*2]     = lo;
                    dst[c*8 + j*2 + 1] = hi;
                }
        }
        __syncthreads();
        #pragma unroll
        for (int oi = 0; oi < 2; ++oi) {
            int idx = tid + (oi << 10);
            int r_ = idx >> 7, cf = idx & 127;
            int rh_ = r_ >> 3, rr = r_ & 7, l = cf >> 2, cc = cf & 3;
            float s = 0.f;
            #pragma unroll
            for (int q = 0; q < 4; ++q)
                s += sm[(((q << 1) | rh_) * 32 + l) * 33 + cc * 8 + rr];
            if (oi) psum1 += s; else psum0 += s;
        }
        __syncthreads();
    }
    #pragma unroll
    for (int oi = 0; oi < 2; ++oi) {
        int idx = tid + (oi << 10);
        int r_ = idx >> 7, cf = idx & 127;
        P[((long long)sp * 16 + r_) * N + (ct << 7) + cf] = oi ? psum1 : psum0;
    }
}

// ---------------- epilogue: split-K reduce + bias + LN + SiLU -> transposed out ----------------
__device__ void ln_silu(const float* __restrict__ P, int ns,
                        const float* __restrict__ bias, const float* __restrict__ gam,
                        const float* __restrict__ bet, float* __restrict__ outT,
                        int b, float* shred)
{
    int j = threadIdx.x;
    float v = bias[j];
    for (int s = 0; s < ns; ++s) v += P[((long long)s * 16 + b) * 1024 + j];
    float m   = block_sum(v, shred) * (1.0f / 1024.0f);
    float d   = v - m;
    float var = block_sum(d * d, shred) * (1.0f / 1024.0f);
    float y   = d * rsqrtf(var + 1e-5f) * gam[j] + bet[j];
    outT[j * 16 + b] = y / (1.0f + expf(-y));
}

// ---------------- categorical ST sample core (warp = one latent slot) ----------------
__device__ __forceinline__ void sample_slot(
    const float* __restrict__ P, int ns, const float* __restrict__ bo,
    const float* __restrict__ gum, int b, int s, int c,
    int& bi, float& sval)
{
    float l = bo[s * 32 + c];
    for (int ks = 0; ks < ns; ++ks) l += P[((long long)ks * 16 + b) * 1024 + s * 32 + c];
    float mx = l;
    #pragma unroll
    for (int o = 16; o; o >>= 1) mx = fmaxf(mx, __shfl_xor_sync(0xffffffffu, mx, o));
    float e  = expf(l - mx);
    float se = e;
    #pragma unroll
    for (int o = 16; o; o >>= 1) se += __shfl_xor_sync(0xffffffffu, se, o);
    float p     = 0.99f * (e / se) + UNI;
    float score = logf(p) + gum[((long long)b * 32 + s) * 32 + c];
    float ms = score;
    #pragma unroll
    for (int o = 16; o; o >>= 1) ms = fmaxf(ms, __shfl_xor_sync(0xffffffffu, ms, o));
    unsigned mk = __ballot_sync(0xffffffffu, score == ms);
    bi = __ffs(mk) - 1;
    float pb = __shfl_sync(0xffffffffu, p, bi);
    sval = (1.0f - pb) + pb;
}

// ---------------- posterior sample + GRU input gather + LN + SiLU ----------------
__device__ void post_sample(const P32& p, int b, int t, float* sm)
{
    float* shred = sm;
    int*   sidx  = (int*)(sm + 32);
    float* ssval = sm + 64;
    int tid = threadIdx.x, s = tid >> 5, c = tid & 31;
    int bi; float sval;
    sample_slot(g_partP, NSH, p.pbo, p.gpost + (long long)t * 16384, b, s, c, bi, sval);
    if (c == 0) { sidx[s] = bi; ssval[s] = sval; }
    __syncthreads();

    float acc = p.gb[tid];
    #pragma unroll 8
    for (int ss = 0; ss < 32; ++ss)
        acc += ssval[ss] * p.gW[(long long)(ss * 32 + sidx[ss]) * 1024 + tid];
    #pragma unroll
    for (int a = 0; a < 6; ++a)
        acc += p.actions[((long long)b * 64 + t) * 6 + a] * p.gW[(long long)(1024 + a) * 1024 + tid];

    float m   = block_sum(acc, shred) * (1.0f / 1024.0f);
    float d   = acc - m;
    float var = block_sum(d * d, shred) * (1.0f / 1024.0f);
    float y   = d * rsqrtf(var + 1e-5f) * p.gg[tid] + p.gB[tid];
    g_xT[tid * 16 + b] = y / (1.0f + expf(-y));
}

// ---------------- prior sample -> feat tail ----------------
__device__ void prior_sample(const P32& p, int b, int t)
{
    int tid = threadIdx.x, s = tid >> 5, c = tid & 31;
    int bi; float sval;
    sample_slot(g_partQ, NSH, p.qbo, p.gprior + (long long)t * 16384, b, s, c, bi, sval);
    p.out[((long long)b * 64 + t) * 5120 + 4096 + s * 32 + c] = (c == bi) ? sval : 0.0f;
}

// ---------------- combined head phases: prior(t) || post(t+1) ----------------
__device__ void run_heads(const P32& p, bool doQ, bool doP, int tp, unsigned& ep, float* sm)
{
    const int G = p.G;
    const int nQ = doQ ? 8 * NSH : 0;
    const int nP = doP ? 8 * NSH : 0;
    // layer 1
    for (int task = (int)blockIdx.x; task < nQ + nP; task += G) {
        if (task < nQ) gemm_task(task, g_deterT, 4096, g_deterT, p.qW1, 1024, 4096, NSH, g_partQ, sm);
        else gemm_task(task - nQ, g_tokT + (long long)tp * 65536, 4096, g_deterT,
                       p.pW1, 1024, 8192, NSH, g_partP, sm);
    }
    gsync(G, ep);
    if (blockIdx.x < 16)       { if (doQ) ln_silu(g_partQ, NSH, p.qb1, p.qg1, p.qB1, g_hQ, blockIdx.x, sm + 8448); }
    else if (blockIdx.x < 32)  { if (doP) ln_silu(g_partP, NSH, p.pb1, p.pg1, p.pB1, g_hP, blockIdx.x - 16, sm + 8448); }
    gsync(G, ep);
    // layer 2
    for (int task = (int)blockIdx.x; task < nQ + nP; task += G) {
        if (task < nQ) gemm_task(task, g_hQ, 1024, g_hQ, p.qW2, 1024, 1024, NSH, g_partQ, sm);
        else gemm_task(task - nQ, g_hP, 1024, g_hP, p.pW2, 1024, 1024, NSH, g_partP, sm);
    }
    gsync(G, ep);
    if (blockIdx.x < 16)       { if (doQ) ln_silu(g_partQ, NSH, p.qb2, p.qg2, p.qB2, g_hQ, blockIdx.x, sm + 8448); }
    else if (blockIdx.x < 32)  { if (doP) ln_silu(g_partP, NSH, p.pb2, p.pg2, p.pB2, g_hP, blockIdx.x - 16, sm + 8448); }
    gsync(G, ep);
    // output layer -> logits partials
    for (int task = (int)blockIdx.x; task < nQ + nP; task += G) {
        if (task < nQ) gemm_task(task, g_hQ, 1024, g_hQ, p.qWo, 1024, 1024, NSH, g_partQ, sm);
        else gemm_task(task - nQ, g_hP, 1024, g_hP, p.pWo, 1024, 1024, NSH, g_partP, sm);
    }
    gsync(G, ep);
}

// ---------------- the persistent kernel ----------------
__global__ void __launch_bounds__(1024, 1) wm_kernel(P32 p)
{
    __shared__ float sm[8448 + 96];
    const int G = p.G;
    unsigned ep = g_epoch;   // stable pre-launch value

    // pre-phase: transpose tokens, zero deter
    for (long long i = (long long)blockIdx.x * 1024 + threadIdx.x; i < 64LL * 4096 * 16; i += (long long)G * 1024) {
        int b = (int)(i & 15), k = (int)((i >> 4) & 4095), t = (int)(i >> 16);
        g_tokT[i] = p.tokens[((long long)b * 64 + t) * 4096 + k];
    }
    for (int i = blockIdx.x * 1024 + threadIdx.x; i < 65536; i += G * 1024)
        g_deterT[i] = 0.0f;
    gsync(G, ep);

    // prologue: post head(0) + sample(0)
    run_heads(p, false, true, 0, ep, sm);
    if (blockIdx.x >= 16 && blockIdx.x < 32) post_sample(p, blockIdx.x - 16, 0, sm);
    gsync(G, ep);

    for (int t = 0; t < 64; ++t) {
        // GRU gate GEMMs (z and c concurrently)
        const int nz = 32 * NSG;
        for (int task = (int)blockIdx.x; task < 2 * nz; task += G) {
            if (task < nz) gemm_task(task, g_xT, 1024, g_deterT, p.gWz, 4096, 5120, NSG, g_partZ, sm);
            else           gemm_task(task - nz, g_xT, 1024, g_deterT, p.gWc, 4096, 5120, NSG, g_partC, sm);
        }
        gsync(G, ep);

        // state update + feat deter write
        if (blockIdx.x < 64) {
            int i = blockIdx.x * 1024 + threadIdx.x;
            int b = i >> 12, n = i & 4095;
            float zp = p.gbz[n], cp = p.gbc[n];
            #pragma unroll
            for (int s = 0; s < NSG; ++s) {
                zp += g_partZ[((long long)s * 16 + b) * 4096 + n];
                cp += g_partC[((long long)s * 16 + b) * 4096 + n];
            }
            float z  = 1.0f / (1.0f + expf(-zp));
            float cd = tanhf(cp);
            float d  = g_deterT[n * 16 + b];
            d = (1.0f - z) * d + z * cd;
            g_deterT[n * 16 + b] = d;
            p.out[((long long)b * 64 + t) * 5120 + n] = d;
        }
        gsync(G, ep);

        // prior head(t) || post head(t+1)
        bool doP = (t < 63);
        run_heads(p, true, doP, t + 1, ep, sm);

        // prior sample(t) || post sample(t+1)
        if (blockIdx.x < 16) prior_sample(p, blockIdx.x, t);
        else if (blockIdx.x < 32 && doP) post_sample(p, blockIdx.x - 16, t + 1, sm);
        gsync(G, ep);
    }
}

// ---------------- launcher: ONE graph node ----------------
extern "C" void kernel_launch(void* const* d_in, const int* in_sizes, int n_in,
                              void* d_out, int out_size)
{
    P32 p;
    p.tokens = (const float*)d_in[0];  p.actions = (const float*)d_in[1];
    p.gpost  = (const float*)d_in[2];  p.gprior  = (const float*)d_in[3];
    p.pW1 = (const float*)d_in[4];  p.pb1 = (const float*)d_in[5];
    p.pg1 = (const float*)d_in[6];  p.pB1 = (const float*)d_in[7];
    p.pW2 = (const float*)d_in[8];  p.pb2 = (const float*)d_in[9];
    p.pg2 = (const float*)d_in[10]; p.pB2 = (const float*)d_in[11];
    p.pWo = (const float*)d_in[12]; p.pbo = (const float*)d_in[13];
    p.qW1 = (const float*)d_in[14]; p.qb1 = (const float*)d_in[15];
    p.qg1 = (const float*)d_in[16]; p.qB1 = (const float*)d_in[17];
    p.qW2 = (const float*)d_in[18]; p.qb2 = (const float*)d_in[19];
    p.qg2 = (const float*)d_in[20]; p.qB2 = (const float*)d_in[21];
    p.qWo = (const float*)d_in[22]; p.qbo = (const float*)d_in[23];
    p.gW  = (const float*)d_in[24]; p.gb  = (const float*)d_in[25];
    p.gg  = (const float*)d_in[26]; p.gB  = (const float*)d_in[27];
    p.gWz = (const float*)d_in[28]; p.gbz = (const float*)d_in[29];
    p.gWc = (const float*)d_in[30]; p.gbc = (const float*)d_in[31];
    p.out = (float*)d_out;

    int dev = 0;
    cudaGetDevice(&dev);
    int numSM = 148;
    cudaDeviceGetAttribute(&numSM, cudaDevAttrMultiProcessorCount, dev);
    p.G = numSM;

    wm_kernel<<<numSM, 1024>>>(p);
}

// round 10
// speedup vs baseline: 1.4675x; 1.4675x over previous
#include <cuda_runtime.h>
#include <cstdint>

typedef unsigned long long u64;

#define NS1 19      // split-K for head layer-1 (K=4096)
#define NS2 9       // split-K for head layer-2 / out (K=1024)
#define NSG 5       // split-K for GRU gates (K=5120)
#define NQMAX 288
static const float UNI = (float)(0.01 / 32.0);

// ---------------- static device scratch (no allocations) ----------------
__device__ __align__(16) float g_tokT[64 * 4096 * 16];   // tokens transposed [t][k][b]
__device__ __align__(16) float g_tok1[64 * 16 * 1024];   // precomputed tok@pW1 [t][b][j]
__device__ __align__(16) float g_deterT[4096 * 16];      // deter transposed [n][b]
__device__ __align__(16) float g_xT[1024 * 16];          // GRU input x transposed
__device__ __align__(16) float g_hQ[1024 * 16];          // prior hidden (transposed)
__device__ __align__(16) float g_hP[1024 * 16];          // post hidden (transposed)
__device__ __align__(16) float g_partQ[NS1 * 16 * 1024];
__device__ __align__(16) float g_partP[NS1 * 16 * 1024];
__device__ __align__(16) float g_partZ[NSG * 16 * 4096];
__device__ __align__(16) float g_partC[NSG * 16 * 4096];
__device__ unsigned g_q[NQMAX];        // dynamic-stealing task counters (one per phase)
__device__ unsigned g_cnt;
__device__ volatile unsigned g_epoch;

struct P32 {
    const float *tokens, *actions, *gpost, *gprior;
    const float *pW1,*pb1,*pg1,*pB1,*pW2,*pb2,*pg2,*pB2,*pWo,*pbo;
    const float *qW1,*qb1,*qg1,*qB1,*qW2,*qb2,*qg2,*qB2,*qWo,*qbo;
    const float *gW,*gb,*gg,*gB,*gWz,*gbz,*gWc,*gbc;
    float* out;
    int G;
};

// ---------------- grid-wide barrier (all G blocks co-resident, grid == #SM) ----------------
__device__ __forceinline__ void gsync(int G, unsigned& ep) {
    __syncthreads();
    ep += 1;
    if (threadIdx.x == 0) {
        __threadfence();
        unsigned v = atomicAdd(&g_cnt, 1u);
        if (v == (unsigned)(G - 1)) {
            atomicExch(&g_cnt, 0u);
            __threadfence();
            g_epoch = ep;
        } else {
            while (g_epoch < ep) { __nanosleep(32); }
        }
        __threadfence();     // gpu-scope -> L1 invalidate
    }
    __syncthreads();
}

// ---------------- dynamic task stealing ----------------
__device__ __forceinline__ int steal(unsigned* q) {
    __shared__ int s_t;
    __syncthreads();
    if (threadIdx.x == 0) s_t = (int)atomicAdd(q, 1u);
    __syncthreads();
    return s_t;
}

// ---------------- block reduction (512 threads) ----------------
__device__ __forceinline__ float block_sum(float v, float* sh) {
    #pragma unroll
    for (int o = 16; o > 0; o >>= 1) v += __shfl_xor_sync(0xffffffffu, v, o);
    if ((threadIdx.x & 31) == 0) sh[threadIdx.x >> 5] = v;
    __syncthreads();
    if (threadIdx.x < 32) {
        float r = (threadIdx.x < 16) ? sh[threadIdx.x] : 0.0f;
        #pragma unroll
        for (int o = 8; o > 0; o >>= 1) r += __shfl_xor_sync(0xffffffffu, r, o);
        if (threadIdx.x == 0) sh[0] = r;
    }
    __syncthreads();
    float r = sh[0];
    __syncthreads();
    return r;
}

// ---------------- GEMM task: P[sp] = X[16,K-slice] @ W[.,128-col tile] ----------------
// X = virtual concat of A0 (len0 k's) and A1, both transposed [k][16].
// 16 warps = 8 k-subranges x 2 row-halves. Lane: 4 cols, 8 rows -> 16 f32x2 accs.
// Inner loop: 4-k batch => 4 weight LDG.128 in flight per warp (MLP=4).
#define COLFMA(WF, A_) do { u64 wd_; \
    asm("mov.b64 %0, {%1, %1};" : "=l"(wd_) : "f"(WF)); \
    asm("fma.rn.f32x2 %0, %1, %2, %0;" : "+l"(acc[(A_)+0]) : "l"(xs0), "l"(wd_)); \
    asm("fma.rn.f32x2 %0, %1, %2, %0;" : "+l"(acc[(A_)+1]) : "l"(xs1), "l"(wd_)); \
    asm("fma.rn.f32x2 %0, %1, %2, %0;" : "+l"(acc[(A_)+2]) : "l"(xs2), "l"(wd_)); \
    asm("fma.rn.f32x2 %0, %1, %2, %0;" : "+l"(acc[(A_)+3]) : "l"(xs3), "l"(wd_)); \
} while (0)

__device__ void gemm_task(
    int ct, int sp,
    const float* __restrict__ A0, int len0, const float* __restrict__ A1,
    const float* __restrict__ W, int N, int K, int NS,
    float* __restrict__ P, float* __restrict__ sm)
{
    const int kb = (int)(((long long)sp * K) / NS);
    const int ke = (int)(((long long)(sp + 1) * K) / NS);
    const int kl = ke - kb;
    const int tid = threadIdx.x;
    const int w = tid >> 5, lane = tid & 31;
    const int rh = w & 1, ks = w >> 1;
    const int wk0 = kb + (int)(((long long)kl * ks) >> 3);
    const int wk1 = kb + (int)(((long long)kl * (ks + 1)) >> 3);
    const int col = (ct << 7) + lane * 4;

    u64 acc[16];
    #pragma unroll
    for (int i = 0; i < 16; ++i) acc[i] = 0ull;

    #pragma unroll 1
    for (int seg = 0; seg < 2; ++seg) {
        int ka = seg ? (wk0 > len0 ? wk0 : len0) : wk0;
        int kz = seg ? wk1 : (wk1 < len0 ? wk1 : len0);
        if (ka >= kz) continue;
        const float* X = (seg ? A1 + (size_t)(ka - len0) * 16
                              : A0 + (size_t)ka * 16) + rh * 8;
        const float* wp = W + (size_t)ka * N + col;
        int n = kz - ka;
        int k = 0;
        #pragma unroll 1
        for (; k + 4 <= n; k += 4) {
            float4 wv[4]; ulonglong2 xa[4], xb[4];
            #pragma unroll
            for (int u = 0; u < 4; ++u) {
                wv[u] = *(const float4*)(wp + (size_t)u * N);
                xa[u] = *(const ulonglong2*)(X + u * 16);
                xb[u] = *(const ulonglong2*)(X + u * 16 + 4);
            }
            #pragma unroll
            for (int u = 0; u < 4; ++u) {
                u64 xs0 = xa[u].x, xs1 = xa[u].y, xs2 = xb[u].x, xs3 = xb[u].y;
                COLFMA(wv[u].x, 0); COLFMA(wv[u].y, 4);
                COLFMA(wv[u].z, 8); COLFMA(wv[u].w, 12);
            }
            wp += (size_t)4 * N; X += 64;
        }
        #pragma unroll 1
        for (; k < n; ++k) {
            float4 wv0 = *(const float4*)wp;
            ulonglong2 xa0 = *(const ulonglong2*)X;
            ulonglong2 xb0 = *(const ulonglong2*)(X + 4);
            u64 xs0 = xa0.x, xs1 = xa0.y, xs2 = xb0.x, xs3 = xb0.y;
            COLFMA(wv0.x, 0); COLFMA(wv0.y, 4);
            COLFMA(wv0.z, 8); COLFMA(wv0.w, 12);
            wp += N; X += 16;
        }
    }

    // cross-warp split-K reduce: 2 rounds x 8 slots through 33-stride smem
    float ps[4] = {0.f, 0.f, 0.f, 0.f};
    #pragma unroll 1
    for (int round = 0; round < 2; ++round) {
        if ((ks >> 2) == round) {
            float* dst = sm + ((((ks & 3) << 1) | rh) * 32 + lane) * 33;
            #pragma unroll
            for (int c = 0; c < 4; ++c)
                #pragma unroll
                for (int j = 0; j < 4; ++j) {
                    float lo, hi;
                    asm("mov.b64 {%0, %1}, %2;" : "=f"(lo), "=f"(hi) : "l"(acc[c*4+j]));
                    dst[c*8 + j*2]     = lo;
                    dst[c*8 + j*2 + 1] = hi;
                }
        }
        __syncthreads();
        #pragma unroll
        for (int oi = 0; oi < 4; ++oi) {
            int idx = tid + (oi << 9);
            int r_ = idx >> 7, cf = idx & 127;
            int rh_ = r_ >> 3, rr = r_ & 7, l = cf >> 2, cc = cf & 3;
            float s = 0.f;
            #pragma unroll
            for (int q = 0; q < 4; ++q)
                s += sm[(((q << 1) | rh_) * 32 + l) * 33 + cc * 8 + rr];
            ps[oi] += s;
        }
        __syncthreads();
    }
    #pragma unroll
    for (int oi = 0; oi < 4; ++oi) {
        int idx = tid + (oi << 9);
        int r_ = idx >> 7, cf = idx & 127;
        P[((size_t)sp * 16 + r_) * N + (ct << 7) + cf] = ps[oi];
    }
}

// ---------------- epilogue: reduce partials + (extra) + bias + LN + SiLU -> transposed ----------------
__device__ void ln_silu(const float* __restrict__ P, int ns, const float* __restrict__ extra,
                        const float* __restrict__ bias, const float* __restrict__ gam,
                        const float* __restrict__ bet, float* __restrict__ outT,
                        int b, float* shred)
{
    int tid = threadIdx.x;
    int j0 = tid, j1 = tid + 512;
    float v0 = bias[j0], v1 = bias[j1];
    if (extra) { v0 += extra[j0]; v1 += extra[j1]; }
    for (int s = 0; s < ns; ++s) {
        const float* row = P + ((size_t)s * 16 + b) * 1024;
        v0 += row[j0]; v1 += row[j1];
    }
    float m   = block_sum(v0 + v1, shred) * (1.0f / 1024.0f);
    float d0 = v0 - m, d1 = v1 - m;
    float var = block_sum(d0*d0 + d1*d1, shred) * (1.0f / 1024.0f);
    float inv = rsqrtf(var + 1e-5f);
    float y0 = d0 * inv * gam[j0] + bet[j0];
    float y1 = d1 * inv * gam[j1] + bet[j1];
    outT[j0 * 16 + b] = y0 / (1.0f + expf(-y0));
    outT[j1 * 16 + b] = y1 / (1.0f + expf(-y1));
}

// ---------------- categorical ST sample (warp = one latent slot) ----------------
__device__ __forceinline__ void sample_slot(
    const float* __restrict__ P, int ns, const float* __restrict__ bo,
    const float* __restrict__ gum, int b, int s, int c,
    int& bi, float& sval)
{
    float l = bo[s * 32 + c];
    for (int ks = 0; ks < ns; ++ks) l += P[((size_t)ks * 16 + b) * 1024 + s * 32 + c];
    float mx = l;
    #pragma unroll
    for (int o = 16; o; o >>= 1) mx = fmaxf(mx, __shfl_xor_sync(0xffffffffu, mx, o));
    float e  = expf(l - mx);
    float se = e;
    #pragma unroll
    for (int o = 16; o; o >>= 1) se += __shfl_xor_sync(0xffffffffu, se, o);
    float p     = 0.99f * (e / se) + UNI;
    float score = logf(p) + gum[((size_t)b * 32 + s) * 32 + c];
    float ms = score;
    #pragma unroll
    for (int o = 16; o; o >>= 1) ms = fmaxf(ms, __shfl_xor_sync(0xffffffffu, ms, o));
    unsigned mk = __ballot_sync(0xffffffffu, score == ms);
    bi = __ffs(mk) - 1;
    float pb = __shfl_sync(0xffffffffu, p, bi);
    sval = (1.0f - pb) + pb;
}

// ---------------- posterior sample + GRU input gather + LN + SiLU ----------------
__device__ void post_sample(const P32& p, int b, int t, float* sm)
{
    float* shred = sm + 8448;
    int*   sidx  = (int*)(sm + 8480);
    float* ssval = sm + 8512;
    int tid = threadIdx.x, w = tid >> 5, c = tid & 31;
    #pragma unroll
    for (int h = 0; h < 2; ++h) {
        int s = w + h * 16;
        int bi; float sval;
        sample_slot(g_partP, NS2, p.pbo, p.gpost + (size_t)t * 16384, b, s, c, bi, sval);
        if (c == 0) { sidx[s] = bi; ssval[s] = sval; }
    }
    __syncthreads();

    float a0, a1;
    {
        int j0 = tid, j1 = tid + 512;
        a0 = p.gb[j0]; a1 = p.gb[j1];
        #pragma unroll 8
        for (int ss = 0; ss < 32; ++ss) {
            const float* row = p.gW + (size_t)(ss * 32 + sidx[ss]) * 1024;
            float sv = ssval[ss];
            a0 += sv * row[j0]; a1 += sv * row[j1];
        }
        #pragma unroll
        for (int a = 0; a < 6; ++a) {
            float av = p.actions[((size_t)b * 64 + t) * 6 + a];
            const float* row = p.gW + (size_t)(1024 + a) * 1024;
            a0 += av * row[j0]; a1 += av * row[j1];
        }
    }
    float m   = block_sum(a0 + a1, shred) * (1.0f / 1024.0f);
    float d0 = a0 - m, d1 = a1 - m;
    float var = block_sum(d0*d0 + d1*d1, shred) * (1.0f / 1024.0f);
    float inv = rsqrtf(var + 1e-5f);
    float y0 = d0 * inv * p.gg[tid] + p.gB[tid];
    float y1 = d1 * inv * p.gg[tid + 512] + p.gB[tid + 512];
    g_xT[tid * 16 + b]         = y0 / (1.0f + expf(-y0));
    g_xT[(tid + 512) * 16 + b] = y1 / (1.0f + expf(-y1));
}

// ---------------- prior sample -> feat tail ----------------
__device__ void prior_sample(const P32& p, int b, int t)
{
    int tid = threadIdx.x, w = tid >> 5, c = tid & 31;
    #pragma unroll
    for (int h = 0; h < 2; ++h) {
        int s = w + h * 16;
        int bi; float sval;
        sample_slot(g_partQ, NS2, p.qbo, p.gprior + (size_t)t * 16384, b, s, c, bi, sval);
        p.out[((size_t)b * 64 + t) * 5120 + 4096 + s * 32 + c] = (c == bi) ? sval : 0.0f;
    }
}

// ---------------- head phases: prior(t) || post(t+1), dynamic stealing ----------------
__device__ void run_heads(const P32& p, bool doQ, bool doP, int tp,
                          unsigned& ep, int& qi, float* sm)
{
    const int G = p.G;
    const bool both = doQ && doP;
    // layer 1 (K=4096; post uses deter-half of pW1, token half precomputed)
    {
        unsigned* q = g_q + (qi++);
        const int nt = both ? 2 * 8 * NS1 : 8 * NS1;
        int task;
        while ((task = steal(q)) < nt) {
            int h, ct, sp;
            if (both) { h = task & 1; ct = (task >> 1) & 7; sp = task >> 4; }
            else      { h = doP ? 1 : 0; ct = task & 7; sp = task >> 3; }
            if (h == 0) gemm_task(ct, sp, g_deterT, 4096, g_deterT, p.qW1, 1024, 4096, NS1, g_partQ, sm);
            else        gemm_task(ct, sp, g_deterT, 4096, g_deterT, p.pW1 + (size_t)4096 * 1024, 1024, 4096, NS1, g_partP, sm);
        }
        gsync(G, ep);
    }
    if (blockIdx.x < 16)      { if (doQ) ln_silu(g_partQ, NS1, nullptr, p.qb1, p.qg1, p.qB1, g_hQ, blockIdx.x, sm + 8448); }
    else if (blockIdx.x < 32) { if (doP) ln_silu(g_partP, NS1, g_tok1 + ((size_t)tp * 16 + (blockIdx.x - 16)) * 1024,
                                                 p.pb1, p.pg1, p.pB1, g_hP, blockIdx.x - 16, sm + 8448); }
    gsync(G, ep);
    // layer 2 (K=1024)
    {
        unsigned* q = g_q + (qi++);
        const int nt = both ? 2 * 8 * NS2 : 8 * NS2;
        int task;
        while ((task = steal(q)) < nt) {
            int h, ct, sp;
            if (both) { h = task & 1; ct = (task >> 1) & 7; sp = task >> 4; }
            else      { h = doP ? 1 : 0; ct = task & 7; sp = task >> 3; }
            if (h == 0) gemm_task(ct, sp, g_hQ, 1024, g_hQ, p.qW2, 1024, 1024, NS2, g_partQ, sm);
            else        gemm_task(ct, sp, g_hP, 1024, g_hP, p.pW2, 1024, 1024, NS2, g_partP, sm);
        }
        gsync(G, ep);
    }
    if (blockIdx.x < 16)      { if (doQ) ln_silu(g_partQ, NS2, nullptr, p.qb2, p.qg2, p.qB2, g_hQ, blockIdx.x, sm + 8448); }
    else if (blockIdx.x < 32) { if (doP) ln_silu(g_partP, NS2, nullptr, p.pb2, p.pg2, p.pB2, g_hP, blockIdx.x - 16, sm + 8448); }
    gsync(G, ep);
    // output layer (K=1024) -> logits partials
    {
        unsigned* q = g_q + (qi++);
        const int nt = both ? 2 * 8 * NS2 : 8 * NS2;
        int task;
        while ((task = steal(q)) < nt) {
            int h, ct, sp;
            if (both) { h = task & 1; ct = (task >> 1) & 7; sp = task >> 4; }
            else      { h = doP ? 1 : 0; ct = task & 7; sp = task >> 3; }
            if (h == 0) gemm_task(ct, sp, g_hQ, 1024, g_hQ, p.qWo, 1024, 1024, NS2, g_partQ, sm);
            else        gemm_task(ct, sp, g_hP, 1024, g_hP, p.pWo, 1024, 1024, NS2, g_partP, sm);
        }
        gsync(G, ep);
    }
}

// ---------------- the persistent kernel ----------------
__global__ void __launch_bounds__(512, 1) wm_kernel(P32 p)
{
    __shared__ float sm[8448 + 96];
    const int G = p.G;
    const int tid = threadIdx.x;
    unsigned ep = g_epoch;    // stable pre-launch value
    int qi = 0;

    // pre-phase: transpose tokens, zero deter, zero task queues
    for (long long i = (long long)blockIdx.x * 512 + tid; i < 64LL * 4096 * 16; i += (long long)G * 512) {
        int b = (int)(i & 15), k = (int)((i >> 4) & 4095), t = (int)(i >> 16);
        g_tokT[i] = p.tokens[((long long)b * 64 + t) * 4096 + k];
    }
    for (int i = blockIdx.x * 512 + tid; i < 65536; i += G * 512) g_deterT[i] = 0.0f;
    if (blockIdx.x == 0 && tid < NQMAX) g_q[tid] = 0u;
    gsync(G, ep);

    // token-half precompute: g_tok1[t][b][:] = tok[b,t] @ pW1[0:4096,:]
    // ct-major task order => consecutive stolen tasks share the weight col-tile (L2 reuse)
    {
        unsigned* q = g_q + (qi++);
        int task;
        while ((task = steal(q)) < 512) {
            int ct = task >> 6, t = task & 63;
            gemm_task(ct, 0, g_tokT + (size_t)t * 65536, 4096, g_tokT,
                      p.pW1, 1024, 4096, 1, g_tok1 + (size_t)t * 16384, sm);
        }
        gsync(G, ep);
    }

    // prologue: post head(0) (deter=0) + sample(0)
    run_heads(p, false, true, 0, ep, qi, sm);
    if (blockIdx.x < 16) post_sample(p, blockIdx.x, 0, sm);
    gsync(G, ep);

    for (int t = 0; t < 64; ++t) {
        // GRU gate GEMMs (z & c interleaved, dynamic stealing)
        {
            unsigned* q = g_q + (qi++);
            int task;
            while ((task = steal(q)) < 2 * 32 * NSG) {
                int m = task & 1, rest = task >> 1;
                int ct = rest & 31, sp = rest >> 5;
                gemm_task(ct, sp, g_xT, 1024, g_deterT,
                          m ? p.gWc : p.gWz, 4096, 5120, NSG,
                          m ? g_partC : g_partZ, sm);
            }
            gsync(G, ep);
        }
        // state update + feat deter write
        {
            int i = blockIdx.x * 512 + tid;
            if (i < 65536) {
                int b = i >> 12, n = i & 4095;
                float zp = p.gbz[n], cp = p.gbc[n];
                #pragma unroll
                for (int s = 0; s < NSG; ++s) {
                    zp += g_partZ[((size_t)s * 16 + b) * 4096 + n];
                    cp += g_partC[((size_t)s * 16 + b) * 4096 + n];
                }
                float z  = 1.0f / (1.0f + expf(-zp));
                float cd = tanhf(cp);
                float d  = g_deterT[n * 16 + b];
                d = (1.0f - z) * d + z * cd;
                g_deterT[n * 16 + b] = d;
                p.out[((size_t)b * 64 + t) * 5120 + n] = d;
            }
            gsync(G, ep);
        }
        // prior head(t) || post head(t+1)
        bool doP = (t < 63);
        run_heads(p, true, doP, t + 1, ep, qi, sm);

        // prior sample(t) || post sample(t+1)
        if (blockIdx.x < 16) prior_sample(p, blockIdx.x, t);
        else if (blockIdx.x < 32 && doP) post_sample(p, blockIdx.x - 16, t + 1, sm);
        gsync(G, ep);
    }
}

// ---------------- launcher: ONE graph node ----------------
extern "C" void kernel_launch(void* const* d_in, const int* in_sizes, int n_in,
                              void* d_out, int out_size)
{
    P32 p;
    p.tokens = (const float*)d_in[0];  p.actions = (const float*)d_in[1];
    p.gpost  = (const float*)d_in[2];  p.gprior  = (const float*)d_in[3];
    p.pW1 = (const float*)d_in[4];  p.pb1 = (const float*)d_in[5];
    p.pg1 = (const float*)d_in[6];  p.pB1 = (const float*)d_in[7];
    p.pW2 = (const float*)d_in[8];  p.pb2 = (const float*)d_in[9];
    p.pg2 = (const float*)d_in[10]; p.pB2 = (const float*)d_in[11];
    p.pWo = (const float*)d_in[12]; p.pbo = (const float*)d_in[13];
    p.qW1 = (const float*)d_in[14]; p.qb1 = (const float*)d_in[15];
    p.qg1 = (const float*)d_in[16]; p.qB1 = (const float*)d_in[17];
    p.qW2 = (const float*)d_in[18]; p.qb2 = (const float*)d_in[19];
    p.qg2 = (const float*)d_in[20]; p.qB2 = (const float*)d_in[21];
    p.qWo = (const float*)d_in[22]; p.qbo = (const float*)d_in[23];
    p.gW  = (const float*)d_in[24]; p.gb  = (const float*)d_in[25];
    p.gg  = (const float*)d_in[26]; p.gB  = (const float*)d_in[27];
    p.gWz = (const float*)d_in[28]; p.gbz = (const float*)d_in[29];
    p.gWc = (const float*)d_in[30]; p.gbc = (const float*)d_in[31];
    p.out = (float*)d_out;

    int dev = 0;
    cudaGetDevice(&dev);
    int numSM = 148;
    cudaDeviceGetAttribute(&numSM, cudaDevAttrMultiProcessorCount, dev);
    p.G = numSM;

    wm_kernel<<<numSM, 512>>>(p);
}

// round 11
// speedup vs baseline: 1.4800x; 1.0085x over previous
#include <cuda_runtime.h>
#include <cstdint>

typedef unsigned long long u64;

#define NS1 19      // split-K for head layer-1 (K=4096)
#define NS2 9       // split-K for head layer-2 / out (K=1024)
#define NSG 5       // split-K for GRU gates (K=5120)
#define NQMAX 288
static const float UNI = (float)(0.01 / 32.0);

// ---------------- static device scratch (no allocations) ----------------
__device__ __align__(16) float g_tokT[64 * 4096 * 16];   // tokens transposed [t][k][b]
__device__ __align__(16) float g_tok1[64 * 16 * 1024];   // precomputed tok@pW1 [t][b][j]
__device__ __align__(16) float g_deterT[4096 * 16];      // deter transposed [n][b]
__device__ __align__(16) float g_xT[1024 * 16];          // GRU input x transposed
__device__ __align__(16) float g_hQ[1024 * 16];          // prior hidden (transposed)
__device__ __align__(16) float g_hP[1024 * 16];          // post hidden (transposed)
__device__ __align__(16) float g_partQ[NS1 * 16 * 1024];
__device__ __align__(16) float g_partP[NS1 * 16 * 1024];
__device__ __align__(16) float g_partZ[NSG * 16 * 4096];
__device__ __align__(16) float g_partC[NSG * 16 * 4096];
__device__ unsigned g_q[NQMAX];        // dynamic-stealing task counters (one per phase)
__device__ unsigned g_cnt;
__device__ volatile unsigned g_epoch;

struct P32 {
    const float *tokens, *actions, *gpost, *gprior;
    const float *pW1,*pb1,*pg1,*pB1,*pW2,*pb2,*pg2,*pB2,*pWo,*pbo;
    const float *qW1,*qb1,*qg1,*qB1,*qW2,*qb2,*qg2,*qB2,*qWo,*qbo;
    const float *gW,*gb,*gg,*gB,*gWz,*gbz,*gWc,*gbc;
    float* out;
    int G;
};

// ---------------- grid-wide barrier (all G blocks co-resident, grid == #SM) ----------------
__device__ __forceinline__ void gsync(int G, unsigned& ep) {
    __syncthreads();
    ep += 1;
    if (threadIdx.x == 0) {
        __threadfence();
        unsigned v = atomicAdd(&g_cnt, 1u);
        if (v == (unsigned)(G - 1)) {
            atomicExch(&g_cnt, 0u);
            __threadfence();
            g_epoch = ep;
        } else {
            while (g_epoch < ep) { __nanosleep(32); }
        }
        __threadfence();     // gpu-scope -> L1 invalidate
    }
    __syncthreads();
}

// ---------------- dynamic task stealing ----------------
__device__ __forceinline__ int steal(unsigned* q) {
    __shared__ int s_t;
    __syncthreads();
    if (threadIdx.x == 0) s_t = (int)atomicAdd(q, 1u);
    __syncthreads();
    return s_t;
}

// ---------------- block reduction (512 threads) ----------------
__device__ __forceinline__ float block_sum(float v, float* sh) {
    #pragma unroll
    for (int o = 16; o > 0; o >>= 1) v += __shfl_xor_sync(0xffffffffu, v, o);
    if ((threadIdx.x & 31) == 0) sh[threadIdx.x >> 5] = v;
    __syncthreads();
    if (threadIdx.x < 32) {
        float r = (threadIdx.x < 16) ? sh[threadIdx.x] : 0.0f;
        #pragma unroll
        for (int o = 8; o > 0; o >>= 1) r += __shfl_xor_sync(0xffffffffu, r, o);
        if (threadIdx.x == 0) sh[0] = r;
    }
    __syncthreads();
    float r = sh[0];
    __syncthreads();
    return r;
}

// ---------------- GEMM task: P[sp] = X[16,K-slice] @ W[.,128-col tile] ----------------
// X = virtual concat of A0 (len0 k's) and A1, both transposed [k][16].
// 16 warps = 8 k-subranges x 2 row-halves. Lane: 4 cols, 8 rows -> 16 f32x2 accs.
// Inner loop: 4-k batch => 4 weight LDG.128 in flight per warp (MLP=4).
#define COLFMA(WF, A_) do { u64 wd_; \
    asm("mov.b64 %0, {%1, %1};" : "=l"(wd_) : "f"(WF)); \
    asm("fma.rn.f32x2 %0, %1, %2, %0;" : "+l"(acc[(A_)+0]) : "l"(xs0), "l"(wd_)); \
    asm("fma.rn.f32x2 %0, %1, %2, %0;" : "+l"(acc[(A_)+1]) : "l"(xs1), "l"(wd_)); \
    asm("fma.rn.f32x2 %0, %1, %2, %0;" : "+l"(acc[(A_)+2]) : "l"(xs2), "l"(wd_)); \
    asm("fma.rn.f32x2 %0, %1, %2, %0;" : "+l"(acc[(A_)+3]) : "l"(xs3), "l"(wd_)); \
} while (0)

__device__ void gemm_task(
    int ct, int sp,
    const float* __restrict__ A0, int len0, const float* __restrict__ A1,
    const float* __restrict__ W, int N, int K, int NS,
    float* __restrict__ P, float* __restrict__ sm)
{
    const int kb = (int)(((long long)sp * K) / NS);
    const int ke = (int)(((long long)(sp + 1) * K) / NS);
    const int kl = ke - kb;
    const int tid = threadIdx.x;
    const int w = tid >> 5, lane = tid & 31;
    const int rh = w & 1, ks = w >> 1;
    const int wk0 = kb + (int)(((long long)kl * ks) >> 3);
    const int wk1 = kb + (int)(((long long)kl * (ks + 1)) >> 3);
    const int col = (ct << 7) + lane * 4;

    u64 acc[16];
    #pragma unroll
    for (int i = 0; i < 16; ++i) acc[i] = 0ull;

    #pragma unroll 1
    for (int seg = 0; seg < 2; ++seg) {
        int ka = seg ? (wk0 > len0 ? wk0 : len0) : wk0;
        int kz = seg ? wk1 : (wk1 < len0 ? wk1 : len0);
        if (ka >= kz) continue;
        const float* X = (seg ? A1 + (size_t)(ka - len0) * 16
                              : A0 + (size_t)ka * 16) + rh * 8;
        const float* wp = W + (size_t)ka * N + col;
        int n = kz - ka;
        int k = 0;
        #pragma unroll 1
        for (; k + 4 <= n; k += 4) {
            float4 wv[4]; ulonglong2 xa[4], xb[4];
            #pragma unroll
            for (int u = 0; u < 4; ++u) {
                wv[u] = *(const float4*)(wp + (size_t)u * N);
                xa[u] = *(const ulonglong2*)(X + u * 16);
                xb[u] = *(const ulonglong2*)(X + u * 16 + 4);
            }
            #pragma unroll
            for (int u = 0; u < 4; ++u) {
                u64 xs0 = xa[u].x, xs1 = xa[u].y, xs2 = xb[u].x, xs3 = xb[u].y;
                COLFMA(wv[u].x, 0); COLFMA(wv[u].y, 4);
                COLFMA(wv[u].z, 8); COLFMA(wv[u].w, 12);
            }
            wp += (size_t)4 * N; X += 64;
        }
        #pragma unroll 1
        for (; k < n; ++k) {
            float4 wv0 = *(const float4*)wp;
            ulonglong2 xa0 = *(const ulonglong2*)X;
            ulonglong2 xb0 = *(const ulonglong2*)(X + 4);
            u64 xs0 = xa0.x, xs1 = xa0.y, xs2 = xb0.x, xs3 = xb0.y;
            COLFMA(wv0.x, 0); COLFMA(wv0.y, 4);
            COLFMA(wv0.z, 8); COLFMA(wv0.w, 12);
            wp += N; X += 16;
        }
    }

    // cross-warp split-K reduce: 2 rounds x 8 slots through 33-stride smem
    float ps[4] = {0.f, 0.f, 0.f, 0.f};
    #pragma unroll 1
    for (int round = 0; round < 2; ++round) {
        if ((ks >> 2) == round) {
            float* dst = sm + ((((ks & 3) << 1) | rh) * 32 + lane) * 33;
            #pragma unroll
            for (int c = 0; c < 4; ++c)
                #pragma unroll
                for (int j = 0; j < 4; ++j) {
                    float lo, hi;
                    asm("mov.b64 {%0, %1}, %2;" : "=f"(lo), "=f"(hi) : "l"(acc[c*4+j]));
                    dst[c*8 + j*2]     = lo;
                    dst[c*8 + j*2 + 1] = hi;
                }
        }
        __syncthreads();
        #pragma unroll
        for (int oi = 0; oi < 4; ++oi) {
            int idx = tid + (oi << 9);
            int r_ = idx >> 7, cf = idx & 127;
            int rh_ = r_ >> 3, rr = r_ & 7, l = cf >> 2, cc = cf & 3;
            float s = 0.f;
            #pragma unroll
            for (int q = 0; q < 4; ++q)
                s += sm[(((q << 1) | rh_) * 32 + l) * 33 + cc * 8 + rr];
            ps[oi] += s;
        }
        __syncthreads();
    }
    #pragma unroll
    for (int oi = 0; oi < 4; ++oi) {
        int idx = tid + (oi << 9);
        int r_ = idx >> 7, cf = idx & 127;
        P[((size_t)sp * 16 + r_) * N + (ct << 7) + cf] = ps[oi];
    }
}

// ---------------- epilogue: reduce partials + (extra) + bias + LN + SiLU -> transposed ----------------
__device__ void ln_silu(const float* __restrict__ P, int ns, const float* __restrict__ extra,
                        const float* __restrict__ bias, const float* __restrict__ gam,
                        const float* __restrict__ bet, float* __restrict__ outT,
                        int b, float* shred)
{
    int tid = threadIdx.x;
    int j0 = tid, j1 = tid + 512;
    float v0 = bias[j0], v1 = bias[j1];
    if (extra) { v0 += extra[j0]; v1 += extra[j1]; }
    for (int s = 0; s < ns; ++s) {
        const float* row = P + ((size_t)s * 16 + b) * 1024;
        v0 += row[j0]; v1 += row[j1];
    }
    float m   = block_sum(v0 + v1, shred) * (1.0f / 1024.0f);
    float d0 = v0 - m, d1 = v1 - m;
    float var = block_sum(d0*d0 + d1*d1, shred) * (1.0f / 1024.0f);
    float inv = rsqrtf(var + 1e-5f);
    float y0 = d0 * inv * gam[j0] + bet[j0];
    float y1 = d1 * inv * gam[j1] + bet[j1];
    outT[j0 * 16 + b] = y0 / (1.0f + expf(-y0));
    outT[j1 * 16 + b] = y1 / (1.0f + expf(-y1));
}

// ---------------- categorical ST sample (warp = one latent slot) ----------------
__device__ __forceinline__ void sample_slot(
    const float* __restrict__ P, int ns, const float* __restrict__ bo,
    const float* __restrict__ gum, int b, int s, int c,
    int& bi, float& sval)
{
    float l = bo[s * 32 + c];
    for (int ks = 0; ks < ns; ++ks) l += P[((size_t)ks * 16 + b) * 1024 + s * 32 + c];
    float mx = l;
    #pragma unroll
    for (int o = 16; o; o >>= 1) mx = fmaxf(mx, __shfl_xor_sync(0xffffffffu, mx, o));
    float e  = expf(l - mx);
    float se = e;
    #pragma unroll
    for (int o = 16; o; o >>= 1) se += __shfl_xor_sync(0xffffffffu, se, o);
    float p     = 0.99f * (e / se) + UNI;
    float score = logf(p) + gum[((size_t)b * 32 + s) * 32 + c];
    float ms = score;
    #pragma unroll
    for (int o = 16; o; o >>= 1) ms = fmaxf(ms, __shfl_xor_sync(0xffffffffu, ms, o));
    unsigned mk = __ballot_sync(0xffffffffu, score == ms);
    bi = __ffs(mk) - 1;
    float pb = __shfl_sync(0xffffffffu, p, bi);
    sval = (1.0f - pb) + pb;
}

// ---------------- posterior sample + GRU input gather + LN + SiLU ----------------
__device__ void post_sample(const P32& p, int b, int t, float* sm)
{
    float* shred = sm + 8448;
    int*   sidx  = (int*)(sm + 8480);
    float* ssval = sm + 8512;
    int tid = threadIdx.x, w = tid >> 5, c = tid & 31;
    #pragma unroll
    for (int h = 0; h < 2; ++h) {
        int s = w + h * 16;
        int bi; float sval;
        sample_slot(g_partP, NS2, p.pbo, p.gpost + (size_t)t * 16384, b, s, c, bi, sval);
        if (c == 0) { sidx[s] = bi; ssval[s] = sval; }
    }
    __syncthreads();

    float a0, a1;
    {
        int j0 = tid, j1 = tid + 512;
        a0 = p.gb[j0]; a1 = p.gb[j1];
        #pragma unroll 8
        for (int ss = 0; ss < 32; ++ss) {
            const float* row = p.gW + (size_t)(ss * 32 + sidx[ss]) * 1024;
            float sv = ssval[ss];
            a0 += sv * row[j0]; a1 += sv * row[j1];
        }
        #pragma unroll
        for (int a = 0; a < 6; ++a) {
            float av = p.actions[((size_t)b * 64 + t) * 6 + a];
            const float* row = p.gW + (size_t)(1024 + a) * 1024;
            a0 += av * row[j0]; a1 += av * row[j1];
        }
    }
    float m   = block_sum(a0 + a1, shred) * (1.0f / 1024.0f);
    float d0 = a0 - m, d1 = a1 - m;
    float var = block_sum(d0*d0 + d1*d1, shred) * (1.0f / 1024.0f);
    float inv = rsqrtf(var + 1e-5f);
    float y0 = d0 * inv * p.gg[tid] + p.gB[tid];
    float y1 = d1 * inv * p.gg[tid + 512] + p.gB[tid + 512];
    g_xT[tid * 16 + b]         = y0 / (1.0f + expf(-y0));
    g_xT[(tid + 512) * 16 + b] = y1 / (1.0f + expf(-y1));
}

// ---------------- prior sample -> feat tail ----------------
__device__ void prior_sample(const P32& p, int b, int t)
{
    int tid = threadIdx.x, w = tid >> 5, c = tid & 31;
    #pragma unroll
    for (int h = 0; h < 2; ++h) {
        int s = w + h * 16;
        int bi; float sval;
        sample_slot(g_partQ, NS2, p.qbo, p.gprior + (size_t)t * 16384, b, s, c, bi, sval);
        p.out[((size_t)b * 64 + t) * 5120 + 4096 + s * 32 + c] = (c == bi) ? sval : 0.0f;
    }
}

// ---------------- head phases: prior(t) || post(t+1), dynamic stealing ----------------
__device__ void run_heads(const P32& p, bool doQ, bool doP, int tp,
                          unsigned& ep, int& qi, float* sm)
{
    const int G = p.G;
    const bool both = doQ && doP;
    // layer 1 (K=4096; post uses deter-half of pW1, token half precomputed)
    {
        unsigned* q = g_q + (qi++);
        const int nt = both ? 2 * 8 * NS1 : 8 * NS1;
        int task;
        while ((task = steal(q)) < nt) {
            int h, ct, sp;
            if (both) { h = task & 1; ct = (task >> 1) & 7; sp = task >> 4; }
            else      { h = doP ? 1 : 0; ct = task & 7; sp = task >> 3; }
            if (h == 0) gemm_task(ct, sp, g_deterT, 4096, g_deterT, p.qW1, 1024, 4096, NS1, g_partQ, sm);
            else        gemm_task(ct, sp, g_deterT, 4096, g_deterT, p.pW1 + (size_t)4096 * 1024, 1024, 4096, NS1, g_partP, sm);
        }
        gsync(G, ep);
    }
    if (blockIdx.x < 16)      { if (doQ) ln_silu(g_partQ, NS1, nullptr, p.qb1, p.qg1, p.qB1, g_hQ, blockIdx.x, sm + 8448); }
    else if (blockIdx.x < 32) { if (doP) ln_silu(g_partP, NS1, g_tok1 + ((size_t)tp * 16 + (blockIdx.x - 16)) * 1024,
                                                 p.pb1, p.pg1, p.pB1, g_hP, blockIdx.x - 16, sm + 8448); }
    gsync(G, ep);
    // layer 2 (K=1024)
    {
        unsigned* q = g_q + (qi++);
        const int nt = both ? 2 * 8 * NS2 : 8 * NS2;
        int task;
        while ((task = steal(q)) < nt) {
            int h, ct, sp;
            if (both) { h = task & 1; ct = (task >> 1) & 7; sp = task >> 4; }
            else      { h = doP ? 1 : 0; ct = task & 7; sp = task >> 3; }
            if (h == 0) gemm_task(ct, sp, g_hQ, 1024, g_hQ, p.qW2, 1024, 1024, NS2, g_partQ, sm);
            else        gemm_task(ct, sp, g_hP, 1024, g_hP, p.pW2, 1024, 1024, NS2, g_partP, sm);
        }
        gsync(G, ep);
    }
    if (blockIdx.x < 16)      { if (doQ) ln_silu(g_partQ, NS2, nullptr, p.qb2, p.qg2, p.qB2, g_hQ, blockIdx.x, sm + 8448); }
    else if (blockIdx.x < 32) { if (doP) ln_silu(g_partP, NS2, nullptr, p.pb2, p.pg2, p.pB2, g_hP, blockIdx.x - 16, sm + 8448); }
    gsync(G, ep);
    // output layer (K=1024) -> logits partials
    {
        unsigned* q = g_q + (qi++);
        const int nt = both ? 2 * 8 * NS2 : 8 * NS2;
        int task;
        while ((task = steal(q)) < nt) {
            int h, ct, sp;
            if (both) { h = task & 1; ct = (task >> 1) & 7; sp = task >> 4; }
            else      { h = doP ? 1 : 0; ct = task & 7; sp = task >> 3; }
            if (h == 0) gemm_task(ct, sp, g_hQ, 1024, g_hQ, p.qWo, 1024, 1024, NS2, g_partQ, sm);
            else        gemm_task(ct, sp, g_hP, 1024, g_hP, p.pWo, 1024, 1024, NS2, g_partP, sm);
        }
        gsync(G, ep);
    }
}

// ---------------- the persistent kernel ----------------
__global__ void __launch_bounds__(512, 1) wm_kernel(P32 p)
{
    __shared__ float sm[8448 + 96];
    const int G = p.G;
    const int tid = threadIdx.x;
    unsigned ep = g_epoch;    // stable pre-launch value
    int qi = 0;

    // pre-phase: transpose tokens, zero deter, zero task queues
    for (long long i = (long long)blockIdx.x * 512 + tid; i < 64LL * 4096 * 16; i += (long long)G * 512) {
        int b = (int)(i & 15), k = (int)((i >> 4) & 4095), t = (int)(i >> 16);
        g_tokT[i] = p.tokens[((long long)b * 64 + t) * 4096 + k];
    }
    for (int i = blockIdx.x * 512 + tid; i < 65536; i += G * 512) g_deterT[i] = 0.0f;
    if (blockIdx.x == 0 && tid < NQMAX) g_q[tid] = 0u;
    gsync(G, ep);

    // token-half precompute: g_tok1[t][b][:] = tok[b,t] @ pW1[0:4096,:]
    // ct-major task order => consecutive stolen tasks share the weight col-tile (L2 reuse)
    {
        unsigned* q = g_q + (qi++);
        int task;
        while ((task = steal(q)) < 512) {
            int ct = task >> 6, t = task & 63;
            gemm_task(ct, 0, g_tokT + (size_t)t * 65536, 4096, g_tokT,
                      p.pW1, 1024, 4096, 1, g_tok1 + (size_t)t * 16384, sm);
        }
        gsync(G, ep);
    }

    // prologue: post head(0) (deter=0) + sample(0)
    run_heads(p, false, true, 0, ep, qi, sm);
    if (blockIdx.x < 16) post_sample(p, blockIdx.x, 0, sm);
    gsync(G, ep);

    for (int t = 0; t < 64; ++t) {
        // GRU gate GEMMs (z & c interleaved, dynamic stealing)
        {
            unsigned* q = g_q + (qi++);
            int task;
            while ((task = steal(q)) < 2 * 32 * NSG) {
                int m = task & 1, rest = task >> 1;
                int ct = rest & 31, sp = rest >> 5;
                gemm_task(ct, sp, g_xT, 1024, g_deterT,
                          m ? p.gWc : p.gWz, 4096, 5120, NSG,
                          m ? g_partC : g_partZ, sm);
            }
            gsync(G, ep);
        }
        // state update + feat deter write
        {
            int i = blockIdx.x * 512 + tid;
            if (i < 65536) {
                int b = i >> 12, n = i & 4095;
                float zp = p.gbz[n], cp = p.gbc[n];
                #pragma unroll
                for (int s = 0; s < NSG; ++s) {
                    zp += g_partZ[((size_t)s * 16 + b) * 4096 + n];
                    cp += g_partC[((size_t)s * 16 + b) * 4096 + n];
                }
                float z  = 1.0f / (1.0f + expf(-zp));
                float cd = tanhf(cp);
                float d  = g_deterT[n * 16 + b];
                d = (1.0f - z) * d + z * cd;
                g_deterT[n * 16 + b] = d;
                p.out[((size_t)b * 64 + t) * 5120 + n] = d;
            }
            gsync(G, ep);
        }
        // prior head(t) || post head(t+1)
        bool doP = (t < 63);
        run_heads(p, true, doP, t + 1, ep, qi, sm);

        // prior sample(t) || post sample(t+1)
        if (blockIdx.x < 16) prior_sample(p, blockIdx.x, t);
        else if (blockIdx.x < 32 && doP) post_sample(p, blockIdx.x - 16, t + 1, sm);
        gsync(G, ep);
    }
}

// ---------------- launcher: ONE graph node ----------------
extern "C" void kernel_launch(void* const* d_in, const int* in_sizes, int n_in,
                              void* d_out, int out_size)
{
    P32 p;
    p.tokens = (const float*)d_in[0];  p.actions = (const float*)d_in[1];
    p.gpost  = (const float*)d_in[2];  p.gprior  = (const float*)d_in[3];
    p.pW1 = (const float*)d_in[4];  p.pb1 = (const float*)d_in[5];
    p.pg1 = (const float*)d_in[6];  p.pB1 = (const float*)d_in[7];
    p.pW2 = (const float*)d_in[8];  p.pb2 = (const float*)d_in[9];
    p.pg2 = (const float*)d_in[10]; p.pB2 = (const float*)d_in[11];
    p.pWo = (const float*)d_in[12]; p.pbo = (const float*)d_in[13];
    p.qW1 = (const float*)d_in[14]; p.qb1 = (const float*)d_in[15];
    p.qg1 = (const float*)d_in[16]; p.qB1 = (const float*)d_in[17];
    p.qW2 = (const float*)d_in[18]; p.qb2 = (const float*)d_in[19];
    p.qg2 = (const float*)d_in[20]; p.qB2 = (const float*)d_in[21];
    p.qWo = (const float*)d_in[22]; p.qbo = (const float*)d_in[23];
    p.gW  = (const float*)d_in[24]; p.gb  = (const float*)d_in[25];
    p.gg  = (const float*)d_in[26]; p.gB  = (const float*)d_in[27];
    p.gWz = (const float*)d_in[28]; p.gbz = (const float*)d_in[29];
    p.gWc = (const float*)d_in[30]; p.gbc = (const float*)d_in[31];
    p.out = (float*)d_out;

    int dev = 0;
    cudaGetDevice(&dev);
    int numSM = 148;
    cudaDeviceGetAttribute(&numSM, cudaDevAttrMultiProcessorCount, dev);
    p.G = numSM;

    wm_kernel<<<numSM, 512>>>(p);
}

// round 15
// speedup vs baseline: 1.8485x; 1.2490x over previous
#include <cuda_runtime.h>
#include <cstdint>

typedef unsigned long long u64;

#define NS1 19      // split-K for head layer-1 (K=4096)
#define NS2 9       // split-K for head layer-2 / out (K=1024)
#define NSG 10      // split-K for GRU gates (K=5120) -> warp range 64, no x/deter straddle
#define NQMAX 288
static const float UNI = (float)(0.01 / 32.0);

// ---------------- static device scratch (no allocations) ----------------
__device__ __align__(16) float g_tokT[64 * 4096 * 16];   // tokens transposed [t][k][b]
__device__ __align__(16) float g_tok1[64 * 16 * 1024];   // precomputed tok@pW1 [t][b][j]
__device__ __align__(16) float g_deterT[4096 * 16];      // deter transposed [n][b]
__device__ __align__(16) float g_xT[1024 * 16];          // GRU input x transposed
__device__ __align__(16) float g_hQ[1024 * 16];          // prior hidden (transposed)
__device__ __align__(16) float g_hP[1024 * 16];          // post hidden (transposed)
__device__ __align__(16) float g_partQ[NS1 * 16 * 1024];
__device__ __align__(16) float g_partP[NS1 * 16 * 1024];
__device__ __align__(16) float g_partZ[NSG * 16 * 4096];
__device__ __align__(16) float g_partC[NSG * 16 * 4096];
__device__ unsigned g_q[NQMAX];        // dynamic-stealing task counters (one per phase)
__device__ unsigned g_cnt;
__device__ volatile unsigned g_epoch;

struct P32 {
    const float *tokens, *actions, *gpost, *gprior;
    const float *pW1,*pb1,*pg1,*pB1,*pW2,*pb2,*pg2,*pB2,*pWo,*pbo;
    const float *qW1,*qb1,*qg1,*qB1,*qW2,*qb2,*qg2,*qB2,*qWo,*qbo;
    const float *gW,*gb,*gg,*gB,*gWz,*gbz,*gWc,*gbc;
    float* out;
    int G;
};

// ---------------- cache-policy weight loads ----------------
// STREAM=true  -> __ldcs (evict-first: GRU gates + one-shot token GEMM; keeps L2 for heads)
// STREAM=false -> __ldg  (cached: head weights become L2-resident across steps)
template<bool STREAM>
__device__ __forceinline__ float4 ldw(const float* p) {
    return STREAM ? __ldcs((const float4*)p) : __ldg((const float4*)p);
}

// ---------------- grid-wide barrier (all G blocks co-resident, grid == #SM) ----------------
__device__ __forceinline__ void gsync(int G, unsigned& ep) {
    __syncthreads();
    ep += 1;
    if (threadIdx.x == 0) {
        __threadfence();
        unsigned v = atomicAdd(&g_cnt, 1u);
        if (v == (unsigned)(G - 1)) {
            atomicExch(&g_cnt, 0u);
            __threadfence();
            g_epoch = ep;
        } else {
            while (g_epoch < ep) { __nanosleep(32); }
        }
        __threadfence();     // gpu-scope -> L1 invalidate
    }
    __syncthreads();
}

// ---------------- dynamic task stealing ----------------
__device__ __forceinline__ int steal(unsigned* q) {
    __shared__ int s_t;
    __syncthreads();
    if (threadIdx.x == 0) s_t = (int)atomicAdd(q, 1u);
    __syncthreads();
    return s_t;
}

// ---------------- block reduction (512 threads) ----------------
__device__ __forceinline__ float block_sum(float v, float* sh) {
    #pragma unroll
    for (int o = 16; o > 0; o >>= 1) v += __shfl_xor_sync(0xffffffffu, v, o);
    if ((threadIdx.x & 31) == 0) sh[threadIdx.x >> 5] = v;
    __syncthreads();
    if (threadIdx.x < 32) {
        float r = (threadIdx.x < 16) ? sh[threadIdx.x] : 0.0f;
        #pragma unroll
        for (int o = 8; o > 0; o >>= 1) r += __shfl_xor_sync(0xffffffffu, r, o);
        if (threadIdx.x == 0) sh[0] = r;
    }
    __syncthreads();
    float r = sh[0];
    __syncthreads();
    return r;
}

// ---------------- GEMM task: P[sp] = X[16,K-slice] @ W[.,128-col tile] ----------------
// X = virtual concat of A0 (len0 k's) and A1, both transposed [k][16].
// 16 warps = 8 k-subranges x 2 row-halves. Lane: 4 cols x 8 rows -> 16 f32x2 accs.
// 8-deep software-pipelined weight prefetch: ~8 LDG.128 (4KB) in flight per warp.
#define COLFMA(WF, A_) do { u64 wd_; \
    asm("mov.b64 %0, {%1, %1};" : "=l"(wd_) : "f"(WF)); \
    asm("fma.rn.f32x2 %0, %1, %2, %0;" : "+l"(acc[(A_)+0]) : "l"(xs0), "l"(wd_)); \
    asm("fma.rn.f32x2 %0, %1, %2, %0;" : "+l"(acc[(A_)+1]) : "l"(xs1), "l"(wd_)); \
    asm("fma.rn.f32x2 %0, %1, %2, %0;" : "+l"(acc[(A_)+2]) : "l"(xs2), "l"(wd_)); \
    asm("fma.rn.f32x2 %0, %1, %2, %0;" : "+l"(acc[(A_)+3]) : "l"(xs3), "l"(wd_)); \
} while (0)

#define XFMA4(WV) do { \
    ulonglong2 xa_ = *(const ulonglong2*)X; \
    ulonglong2 xb_ = *(const ulonglong2*)(X + 4); \
    u64 xs0 = xa_.x, xs1 = xa_.y, xs2 = xb_.x, xs3 = xb_.y; \
    COLFMA((WV).x, 0); COLFMA((WV).y, 4); \
    COLFMA((WV).z, 8); COLFMA((WV).w, 12); \
    X += 16; \
} while (0)

template<bool STREAM>
__device__ void gemm_task(
    int ct, int sp,
    const float* __restrict__ A0, int len0, const float* __restrict__ A1,
    const float* __restrict__ W, int N, int K, int NS,
    float* __restrict__ P, float* __restrict__ sm)
{
    const int kb = (int)(((long long)sp * K) / NS);
    const int ke = (int)(((long long)(sp + 1) * K) / NS);
    const int kl = ke - kb;
    const int tid = threadIdx.x;
    const int w = tid >> 5, lane = tid & 31;
    const int rh = w & 1, ks = w >> 1;
    const int wk0 = kb + (int)(((long long)kl * ks) >> 3);
    const int wk1 = kb + (int)(((long long)kl * (ks + 1)) >> 3);
    const int col = (ct << 7) + lane * 4;

    u64 acc[16];
    #pragma unroll
    for (int i = 0; i < 16; ++i) acc[i] = 0ull;

    #pragma unroll 1
    for (int seg = 0; seg < 2; ++seg) {
        int ka = seg ? (wk0 > len0 ? wk0 : len0) : wk0;
        int kz = seg ? wk1 : (wk1 < len0 ? wk1 : len0);
        if (ka >= kz) continue;
        const float* X = (seg ? A1 + (size_t)(ka - len0) * 16
                              : A0 + (size_t)ka * 16) + rh * 8;
        const float* wp = W + (size_t)ka * N + col;
        const int n = kz - ka;
        const int n8 = n & ~7;

        if (n8) {
            float4 Wb[8];
            #pragma unroll
            for (int u = 0; u < 8; ++u) Wb[u] = ldw<STREAM>(wp + (size_t)u * N);
            #pragma unroll 1
            for (int k = 8; k < n8; k += 8) {
                #pragma unroll
                for (int u = 0; u < 8; ++u) {
                    float4 wv = Wb[u];
                    Wb[u] = ldw<STREAM>(wp + (size_t)(k + u) * N);   // prefetch next batch
                    XFMA4(wv);
                }
            }
            #pragma unroll
            for (int u = 0; u < 8; ++u) { float4 wv = Wb[u]; XFMA4(wv); }
        }
        #pragma unroll 1
        for (int k = n8; k < n; ++k) {
            float4 wv = ldw<STREAM>(wp + (size_t)k * N);
            XFMA4(wv);
        }
    }

    // cross-warp split-K reduce: 2 rounds x 8 slots through 33-stride smem
    float ps[4] = {0.f, 0.f, 0.f, 0.f};
    #pragma unroll 1
    for (int round = 0; round < 2; ++round) {
        if ((ks >> 2) == round) {
            float* dst = sm + ((((ks & 3) << 1) | rh) * 32 + lane) * 33;
            #pragma unroll
            for (int c = 0; c < 4; ++c)
                #pragma unroll
                for (int j = 0; j < 4; ++j) {
                    float lo, hi;
                    asm("mov.b64 {%0, %1}, %2;" : "=f"(lo), "=f"(hi) : "l"(acc[c*4+j]));
                    dst[c*8 + j*2]     = lo;
                    dst[c*8 + j*2 + 1] = hi;
                }
        }
        __syncthreads();
        #pragma unroll
        for (int oi = 0; oi < 4; ++oi) {
            int idx = tid + (oi << 9);
            int r_ = idx >> 7, cf = idx & 127;
            int rh_ = r_ >> 3, rr = r_ & 7, l = cf >> 2, cc = cf & 3;
            float s = 0.f;
            #pragma unroll
            for (int q = 0; q < 4; ++q)
                s += sm[(((q << 1) | rh_) * 32 + l) * 33 + cc * 8 + rr];
            ps[oi] += s;
        }
        __syncthreads();
    }
    #pragma unroll
    for (int oi = 0; oi < 4; ++oi) {
        int idx = tid + (oi << 9);
        int r_ = idx >> 7, cf = idx & 127;
        P[((size_t)sp * 16 + r_) * N + (ct << 7) + cf] = ps[oi];
    }
}

// ---------------- epilogue: reduce partials + (extra) + bias + LN + SiLU -> transposed ----------------
__device__ void ln_silu(const float* __restrict__ P, int ns, const float* __restrict__ extra,
                        const float* __restrict__ bias, const float* __restrict__ gam,
                        const float* __restrict__ bet, float* __restrict__ outT,
                        int b, float* shred)
{
    int tid = threadIdx.x;
    int j0 = tid, j1 = tid + 512;
    float v0 = bias[j0], v1 = bias[j1];
    if (extra) { v0 += extra[j0]; v1 += extra[j1]; }
    for (int s = 0; s < ns; ++s) {
        const float* row = P + ((size_t)s * 16 + b) * 1024;
        v0 += row[j0]; v1 += row[j1];
    }
    float m   = block_sum(v0 + v1, shred) * (1.0f / 1024.0f);
    float d0 = v0 - m, d1 = v1 - m;
    float var = block_sum(d0*d0 + d1*d1, shred) * (1.0f / 1024.0f);
    float inv = rsqrtf(var + 1e-5f);
    float y0 = d0 * inv * gam[j0] + bet[j0];
    float y1 = d1 * inv * gam[j1] + bet[j1];
    outT[j0 * 16 + b] = y0 / (1.0f + expf(-y0));
    outT[j1 * 16 + b] = y1 / (1.0f + expf(-y1));
}

// ---------------- categorical ST sample (warp = one latent slot) ----------------
__device__ __forceinline__ void sample_slot(
    const float* __restrict__ P, int ns, const float* __restrict__ bo,
    const float* __restrict__ gum, int b, int s, int c,
    int& bi, float& sval)
{
    float l = bo[s * 32 + c];
    for (int ks = 0; ks < ns; ++ks) l += P[((size_t)ks * 16 + b) * 1024 + s * 32 + c];
    float mx = l;
    #pragma unroll
    for (int o = 16; o; o >>= 1) mx = fmaxf(mx, __shfl_xor_sync(0xffffffffu, mx, o));
    float e  = expf(l - mx);
    float se = e;
    #pragma unroll
    for (int o = 16; o; o >>= 1) se += __shfl_xor_sync(0xffffffffu, se, o);
    float p     = 0.99f * (e / se) + UNI;
    float score = logf(p) + gum[((size_t)b * 32 + s) * 32 + c];
    float ms = score;
    #pragma unroll
    for (int o = 16; o; o >>= 1) ms = fmaxf(ms, __shfl_xor_sync(0xffffffffu, ms, o));
    unsigned mk = __ballot_sync(0xffffffffu, score == ms);
    bi = __ffs(mk) - 1;
    float pb = __shfl_sync(0xffffffffu, p, bi);
    sval = (1.0f - pb) + pb;
}

// ---------------- posterior sample + GRU input gather + LN + SiLU ----------------
__device__ void post_sample(const P32& p, int b, int t, float* sm)
{
    float* shred = sm + 8448;
    int*   sidx  = (int*)(sm + 8480);
    float* ssval = sm + 8512;
    int tid = threadIdx.x, w = tid >> 5, c = tid & 31;
    #pragma unroll
    for (int h = 0; h < 2; ++h) {
        int s = w + h * 16;
        int bi; float sval;
        sample_slot(g_partP, NS2, p.pbo, p.gpost + (size_t)t * 16384, b, s, c, bi, sval);
        if (c == 0) { sidx[s] = bi; ssval[s] = sval; }
    }
    __syncthreads();

    float a0, a1;
    {
        int j0 = tid, j1 = tid + 512;
        a0 = p.gb[j0]; a1 = p.gb[j1];
        #pragma unroll 8
        for (int ss = 0; ss < 32; ++ss) {
            const float* row = p.gW + (size_t)(ss * 32 + sidx[ss]) * 1024;
            float sv = ssval[ss];
            a0 += sv * row[j0]; a1 += sv * row[j1];
        }
        #pragma unroll
        for (int a = 0; a < 6; ++a) {
            float av = p.actions[((size_t)b * 64 + t) * 6 + a];
            const float* row = p.gW + (size_t)(1024 + a) * 1024;
            a0 += av * row[j0]; a1 += av * row[j1];
        }
    }
    float m   = block_sum(a0 + a1, shred) * (1.0f / 1024.0f);
    float d0 = a0 - m, d1 = a1 - m;
    float var = block_sum(d0*d0 + d1*d1, shred) * (1.0f / 1024.0f);
    float inv = rsqrtf(var + 1e-5f);
    float y0 = d0 * inv * p.gg[tid] + p.gB[tid];
    float y1 = d1 * inv * p.gg[tid + 512] + p.gB[tid + 512];
    g_xT[tid * 16 + b]         = y0 / (1.0f + expf(-y0));
    g_xT[(tid + 512) * 16 + b] = y1 / (1.0f + expf(-y1));
}

// ---------------- prior sample -> feat tail ----------------
__device__ void prior_sample(const P32& p, int b, int t)
{
    int tid = threadIdx.x, w = tid >> 5, c = tid & 31;
    #pragma unroll
    for (int h = 0; h < 2; ++h) {
        int s = w + h * 16;
        int bi; float sval;
        sample_slot(g_partQ, NS2, p.qbo, p.gprior + (size_t)t * 16384, b, s, c, bi, sval);
        p.out[((size_t)b * 64 + t) * 5120 + 4096 + s * 32 + c] = (c == bi) ? sval : 0.0f;
    }
}

// ---------------- head phases: prior(t) || post(t+1), dynamic stealing ----------------
__device__ void run_heads(const P32& p, bool doQ, bool doP, int tp,
                          unsigned& ep, int& qi, float* sm)
{
    const int G = p.G;
    const bool both = doQ && doP;
    // layer 1 (K=4096; post uses deter-half of pW1, token half precomputed)
    {
        unsigned* q = g_q + (qi++);
        const int nt = both ? 2 * 8 * NS1 : 8 * NS1;
        int task;
        while ((task = steal(q)) < nt) {
            int h, ct, sp;
            if (both) { h = task & 1; ct = (task >> 1) & 7; sp = task >> 4; }
            else      { h = doP ? 1 : 0; ct = task & 7; sp = task >> 3; }
            if (h == 0) gemm_task<false>(ct, sp, g_deterT, 4096, g_deterT, p.qW1, 1024, 4096, NS1, g_partQ, sm);
            else        gemm_task<false>(ct, sp, g_deterT, 4096, g_deterT, p.pW1 + (size_t)4096 * 1024, 1024, 4096, NS1, g_partP, sm);
        }
        gsync(G, ep);
    }
    if (blockIdx.x < 16)      { if (doQ) ln_silu(g_partQ, NS1, nullptr, p.qb1, p.qg1, p.qB1, g_hQ, blockIdx.x, sm + 8448); }
    else if (blockIdx.x < 32) { if (doP) ln_silu(g_partP, NS1, g_tok1 + ((size_t)tp * 16 + (blockIdx.x - 16)) * 1024,
                                                 p.pb1, p.pg1, p.pB1, g_hP, blockIdx.x - 16, sm + 8448); }
    gsync(G, ep);
    // layer 2 (K=1024)
    {
        unsigned* q = g_q + (qi++);
        const int nt = both ? 2 * 8 * NS2 : 8 * NS2;
        int task;
        while ((task = steal(q)) < nt) {
            int h, ct, sp;
            if (both) { h = task & 1; ct = (task >> 1) & 7; sp = task >> 4; }
            else      { h = doP ? 1 : 0; ct = task & 7; sp = task >> 3; }
            if (h == 0) gemm_task<false>(ct, sp, g_hQ, 1024, g_hQ, p.qW2, 1024, 1024, NS2, g_partQ, sm);
            else        gemm_task<false>(ct, sp, g_hP, 1024, g_hP, p.pW2, 1024, 1024, NS2, g_partP, sm);
        }
        gsync(G, ep);
    }
    if (blockIdx.x < 16)      { if (doQ) ln_silu(g_partQ, NS2, nullptr, p.qb2, p.qg2, p.qB2, g_hQ, blockIdx.x, sm + 8448); }
    else if (blockIdx.x < 32) { if (doP) ln_silu(g_partP, NS2, nullptr, p.pb2, p.pg2, p.pB2, g_hP, blockIdx.x - 16, sm + 8448); }
    gsync(G, ep);
    // output layer (K=1024) -> logits partials
    {
        unsigned* q = g_q + (qi++);
        const int nt = both ? 2 * 8 * NS2 : 8 * NS2;
        int task;
        while ((task = steal(q)) < nt) {
            int h, ct, sp;
            if (both) { h = task & 1; ct = (task >> 1) & 7; sp = task >> 4; }
            else      { h = doP ? 1 : 0; ct = task & 7; sp = task >> 3; }
            if (h == 0) gemm_task<false>(ct, sp, g_hQ, 1024, g_hQ, p.qWo, 1024, 1024, NS2, g_partQ, sm);
            else        gemm_task<false>(ct, sp, g_hP, 1024, g_hP, p.pWo, 1024, 1024, NS2, g_partP, sm);
        }
        gsync(G, ep);
    }
}

// ---------------- the persistent kernel ----------------
__global__ void __launch_bounds__(512, 1) wm_kernel(P32 p)
{
    __shared__ float sm[8448 + 96];
    const int G = p.G;
    const int tid = threadIdx.x;
    unsigned ep = g_epoch;    // stable pre-launch value
    int qi = 0;

    // pre-phase: transpose tokens, zero deter, zero task queues
    for (long long i = (long long)blockIdx.x * 512 + tid; i < 64LL * 4096 * 16; i += (long long)G * 512) {
        int b = (int)(i & 15), k = (int)((i >> 4) & 4095), t = (int)(i >> 16);
        g_tokT[i] = p.tokens[((long long)b * 64 + t) * 4096 + k];
    }
    for (int i = blockIdx.x * 512 + tid; i < 65536; i += G * 512) g_deterT[i] = 0.0f;
    if (blockIdx.x == 0 && tid < NQMAX) g_q[tid] = 0u;
    gsync(G, ep);

    // token-half precompute: g_tok1[t][b][:] = tok[b,t] @ pW1[0:4096,:]   (streamed weights)
    {
        unsigned* q = g_q + (qi++);
        int task;
        while ((task = steal(q)) < 512) {
            int ct = task >> 6, t = task & 63;
            gemm_task<true>(ct, 0, g_tokT + (size_t)t * 65536, 4096, g_tokT,
                            p.pW1, 1024, 4096, 1, g_tok1 + (size_t)t * 16384, sm);
        }
        gsync(G, ep);
    }

    // prologue: post head(0) (deter=0) + sample(0)
    run_heads(p, false, true, 0, ep, qi, sm);
    if (blockIdx.x < 16) post_sample(p, blockIdx.x, 0, sm);
    gsync(G, ep);

    for (int t = 0; t < 64; ++t) {
        // GRU gate GEMMs (z & c interleaved, streamed weights, dynamic stealing)
        {
            unsigned* q = g_q + (qi++);
            int task;
            while ((task = steal(q)) < 2 * 32 * NSG) {
                int m = task & 1;
                int ct = (task >> 1) & 31, sp = task >> 6;
                gemm_task<true>(ct, sp, g_xT, 1024, g_deterT,
                                m ? p.gWc : p.gWz, 4096, 5120, NSG,
                                m ? g_partC : g_partZ, sm);
            }
            gsync(G, ep);
        }
        // state update + feat deter write
        {
            int i = blockIdx.x * 512 + tid;
            if (i < 65536) {
                int b = i >> 12, n = i & 4095;
                float zp = p.gbz[n], cp = p.gbc[n];
                #pragma unroll
                for (int s = 0; s < NSG; ++s) {
                    zp += g_partZ[((size_t)s * 16 + b) * 4096 + n];
                    cp += g_partC[((size_t)s * 16 + b) * 4096 + n];
                }
                float z  = 1.0f / (1.0f + expf(-zp));
                float cd = tanhf(cp);
                float d  = g_deterT[n * 16 + b];
                d = (1.0f - z) * d + z * cd;
                g_deterT[n * 16 + b] = d;
                p.out[((size_t)b * 64 + t) * 5120 + n] = d;
            }
            gsync(G, ep);
        }
        // prior head(t) || post head(t+1)
        bool doP = (t < 63);
        run_heads(p, true, doP, t + 1, ep, qi, sm);

        // prior sample(t) || post sample(t+1)
        if (blockIdx.x < 16) prior_sample(p, blockIdx.x, t);
        else if (blockIdx.x < 32 && doP) post_sample(p, blockIdx.x - 16, t + 1, sm);
        gsync(G, ep);
    }
}

// ---------------- launcher: ONE graph node ----------------
extern "C" void kernel_launch(void* const* d_in, const int* in_sizes, int n_in,
                              void* d_out, int out_size)
{
    P32 p;
    p.tokens = (const float*)d_in[0];  p.actions = (const float*)d_in[1];
    p.gpost  = (const float*)d_in[2];  p.gprior  = (const float*)d_in[3];
    p.pW1 = (const float*)d_in[4];  p.pb1 = (const float*)d_in[5];
    p.pg1 = (const float*)d_in[6];  p.pB1 = (const float*)d_in[7];
    p.pW2 = (const float*)d_in[8];  p.pb2 = (const float*)d_in[9];
    p.pg2 = (const float*)d_in[10]; p.pB2 = (const float*)d_in[11];
    p.pWo = (const float*)d_in[12]; p.pbo = (const float*)d_in[13];
    p.qW1 = (const float*)d_in[14]; p.qb1 = (const float*)d_in[15];
    p.qg1 = (const float*)d_in[16]; p.qB1 = (const float*)d_in[17];
    p.qW2 = (const float*)d_in[18]; p.qb2 = (const float*)d_in[19];
    p.qg2 = (const float*)d_in[20]; p.qB2 = (const float*)d_in[21];
    p.qWo = (const float*)d_in[22]; p.qbo = (const float*)d_in[23];
    p.gW  = (const float*)d_in[24]; p.gb  = (const float*)d_in[25];
    p.gg  = (const float*)d_in[26]; p.gB  = (const float*)d_in[27];
    p.gWz = (const float*)d_in[28]; p.gbz = (const float*)d_in[29];
    p.gWc = (const float*)d_in[30]; p.gbc = (const float*)d_in[31];
    p.out = (float*)d_out;

    int dev = 0;
    cudaGetDevice(&dev);
    int numSM = 148;
    cudaDeviceGetAttribute(&numSM, cudaDevAttrMultiProcessorCount, dev);
    p.G = numSM;

    wm_kernel<<<numSM, 512>>>(p);
}